// round 16
// baseline (speedup 1.0000x reference)
#include <cuda_runtime.h>
#include <cuda_bf16.h>
#include <math.h>
#include <stdint.h>

// ---------------------------------------------------------------------------
// GPT forward: B=8, S=512, D=768, H=12, dh=64, L=12, FF=3072, M = 4096
// GEMMs on mma.sync bf16 (3-term hi/lo split, 256x128 CTA tile, BK=64,
// double-buffered, split-K); qkv emitted as bf16 hi/lo; flash attention
// reads bf16 directly via cp.async; weight conversion hoisted; HW tanh gelu.
// ---------------------------------------------------------------------------
#define BB 8
#define SS 512
#define DD 768
#define HH 12
#define DH 64
#define LL 12
#define FF 3072
#define MM (BB * SS)       // 4096
#define BH (BB * HH)       // 96
#define QD (3 * DD)        // 2304

// ---------------- scratch (static device globals; no allocation) -----------
__device__ float g_h[MM * DD];
__device__ float g_n[MM * DD];
__device__ float g_qkv[MM * 3 * DD];   // 3 split-K fp32 partials of [MM,DD]
__device__ __nv_bfloat16 g_Ah[(size_t)MM * DD];
__device__ __nv_bfloat16 g_Al[(size_t)MM * DD];
__device__ __nv_bfloat16 g_Fh[(size_t)MM * FF];   // fc1 out OR qkv hi
__device__ __nv_bfloat16 g_Fl[(size_t)MM * FF];   // fc1 out OR qkv lo
// all-layer split weights, transposed [N,K]
__device__ __nv_bfloat16 g_Wqkv_h[(size_t)LL * 3 * DD * DD];
__device__ __nv_bfloat16 g_Wqkv_l[(size_t)LL * 3 * DD * DD];
__device__ __nv_bfloat16 g_Wo_h[(size_t)LL * DD * DD];
__device__ __nv_bfloat16 g_Wo_l[(size_t)LL * DD * DD];
__device__ __nv_bfloat16 g_Wfc_h[(size_t)LL * FF * DD];
__device__ __nv_bfloat16 g_Wfc_l[(size_t)LL * FF * DD];
__device__ __nv_bfloat16 g_Wp2_h[(size_t)LL * DD * FF];
__device__ __nv_bfloat16 g_Wp2_l[(size_t)LL * DD * FF];

// ---------------- helpers ----------------------------------------------------
__device__ __forceinline__ uint32_t smem_u32(const void* p) {
    uint32_t a;
    asm("{ .reg .u64 t; cvta.to.shared.u64 t, %1; cvt.u32.u64 %0, t; }" : "=r"(a) : "l"(p));
    return a;
}
#define CP16(dst, src) asm volatile("cp.async.cg.shared.global [%0], [%1], 16;" :: "r"((uint32_t)(dst)), "l"(src) : "memory")
#define CP_COMMIT()    asm volatile("cp.async.commit_group;" ::: "memory")
#define CP_WAIT(n)     asm volatile("cp.async.wait_group %0;" :: "n"(n) : "memory")

__device__ __forceinline__ void ldm4(uint32_t* r, uint32_t addr) {
    asm volatile("ldmatrix.sync.aligned.m8n8.x4.shared.b16 {%0,%1,%2,%3}, [%4];"
                 : "=r"(r[0]), "=r"(r[1]), "=r"(r[2]), "=r"(r[3]) : "r"(addr));
}
__device__ __forceinline__ void ldm4t(uint32_t* r, uint32_t addr) {
    asm volatile("ldmatrix.sync.aligned.m8n8.x4.trans.shared.b16 {%0,%1,%2,%3}, [%4];"
                 : "=r"(r[0]), "=r"(r[1]), "=r"(r[2]), "=r"(r[3]) : "r"(addr));
}
__device__ __forceinline__ void mma_bf16(float* c, const uint32_t* a, const uint32_t* b) {
    asm volatile(
        "mma.sync.aligned.m16n8k16.row.col.f32.bf16.bf16.f32 "
        "{%0,%1,%2,%3}, {%4,%5,%6,%7}, {%8,%9}, {%0,%1,%2,%3};"
        : "+f"(c[0]), "+f"(c[1]), "+f"(c[2]), "+f"(c[3])
        : "r"(a[0]), "r"(a[1]), "r"(a[2]), "r"(a[3]), "r"(b[0]), "r"(b[1]));
}

__device__ __forceinline__ float tanh_fast(float x) {
    float r;
    asm("tanh.approx.f32 %0, %1;" : "=f"(r) : "f"(x));
    return r;
}
__device__ __forceinline__ float gelu_tanh(float x) {
    float x3 = x * x * x;
    return 0.5f * x * (1.0f + tanh_fast(0.7978845608028654f * (x + 0.044715f * x3)));
}
__device__ __forceinline__ void split2(float x, float y, __nv_bfloat16* hi, __nv_bfloat16* lo) {
    __nv_bfloat16 h0 = __float2bfloat16(x), h1 = __float2bfloat16(y);
    *(__nv_bfloat162*)hi = __nv_bfloat162(h0, h1);
    *(__nv_bfloat162*)lo = __nv_bfloat162(__float2bfloat16(x - __bfloat162float(h0)),
                                          __float2bfloat16(y - __bfloat162float(h1)));
}
__device__ __forceinline__ void pack2(float x, float y, uint32_t* hi, uint32_t* lo) {
    __nv_bfloat162 h(__float2bfloat16(x), __float2bfloat16(y));
    *hi = *(uint32_t*)&h;
    __nv_bfloat162 l(__float2bfloat16(x - __bfloat162float(h.x)),
                     __float2bfloat16(y - __bfloat162float(h.y)));
    *lo = *(uint32_t*)&l;
}

template <int WARPS>
__device__ __forceinline__ float block_sum(float v, float* sh) {
    int t = threadIdx.x;
#pragma unroll
    for (int o = 16; o > 0; o >>= 1) v += __shfl_xor_sync(0xffffffffu, v, o);
    if ((t & 31) == 0) sh[t >> 5] = v;
    __syncthreads();
    if (t == 0) {
        float s = sh[0];
#pragma unroll
        for (int w = 1; w < WARPS; w++) s += sh[w];
        sh[0] = s;
    }
    __syncthreads();
    float r = sh[0];
    __syncthreads();
    return r;
}

// ---------------- embedding (+ bf16 split) ----------------------------------
__global__ __launch_bounds__(256) void embed_kernel(
    const int* __restrict__ ids, const float* __restrict__ tok,
    const float* __restrict__ pos, float* __restrict__ h,
    __nv_bfloat16* __restrict__ hi, __nv_bfloat16* __restrict__ lo) {
    int i = (blockIdx.x * 256 + threadIdx.x) * 2;
    if (i >= MM * DD) return;
    int row = i / DD;
    int c = i - row * DD;
    int s = row & (SS - 1);
    size_t tb = (size_t)ids[row] * DD + c;
    size_t pb = (size_t)s * DD + c;
    float v0 = tok[tb] + pos[pb];
    float v1 = tok[tb + 1] + pos[pb + 1];
    h[i] = v0; h[i + 1] = v1;
    split2(v0, v1, hi + i, lo + i);
}

// ---------------- weight transpose+split (all layers): W[l][K,N] -> [l][N,K]
__global__ __launch_bounds__(256) void conv_wT(
    const float* __restrict__ W, __nv_bfloat16* __restrict__ Whi,
    __nv_bfloat16* __restrict__ Wlo, int K, int N) {
    __shared__ float t[32][33];
    int tx = threadIdx.x & 31;
    int ty = threadIdx.x >> 5;
    int bx = blockIdx.x;
    int by = blockIdx.y;
    size_t lofs = (size_t)blockIdx.z * K * N;
    const float* Wl_ = W + lofs;
    __nv_bfloat16* Hh = Whi + lofs;
    __nv_bfloat16* Hl = Wlo + lofs;
#pragma unroll
    for (int i = 0; i < 4; i++)
        t[ty + i * 8][tx] = Wl_[(size_t)(by * 32 + ty + i * 8) * N + bx * 32 + tx];
    __syncthreads();
    const int kk = (threadIdx.x & 15) * 2;
    const int nn0 = threadIdx.x >> 4;
#pragma unroll
    for (int i = 0; i < 2; i++) {
        int nn = nn0 + i * 16;
        float v0 = t[kk][nn];
        float v1 = t[kk + 1][nn];
        uint32_t uh, ul;
        pack2(v0, v1, &uh, &ul);
        size_t idx = (size_t)(bx * 32 + nn) * K + by * 32 + kk;
        *(uint32_t*)&Hh[idx] = uh;
        *(uint32_t*)&Hl[idx] = ul;
    }
}

// ---------------- bf16 mma.sync GEMM: C = A[M,K] @ Wt[N,K]^T + bias ---------
// CTA 256(M)x128(N), BK=64, 8 warps (4M x 2N), warp tile 64x64, double buffer.
// mode 0: fp32 C (split-K via gridDim.z). mode 1: gelu + bf16 hi/lo.
// mode 2: bf16 hi/lo (no gelu).
#define GRS 144
#define GA_ARR (256 * GRS)
#define GW_ARR (128 * GRS)
#define GSTAGE (2 * GA_ARR + 2 * GW_ARR)   // 110592
#define GEMM_SMEM (2 * GSTAGE)             // 221184

__global__ void __launch_bounds__(256, 1) gemm_mma(
    const __nv_bfloat16* __restrict__ Ah, const __nv_bfloat16* __restrict__ Al,
    const __nv_bfloat16* __restrict__ Wh, const __nv_bfloat16* __restrict__ Wl,
    const float* __restrict__ bias, float* __restrict__ C,
    __nv_bfloat16* __restrict__ Ch, __nv_bfloat16* __restrict__ Cl,
    int N, int K, int mode) {
    extern __shared__ __align__(128) char smem[];
    const uint32_t sb = smem_u32(smem);

    const int tid = threadIdx.x;
    const int wid = tid >> 5;
    const int lane = tid & 31;
    const int wm = wid & 3;
    const int wn = wid >> 2;
    const int m0 = blockIdx.y * 256;
    const int n0 = blockIdx.x * 128;
    const int ksl = K / gridDim.z;
    const int kbase = blockIdx.z * ksl;
    const int nchunks = ksl >> 6;
    float* Cz = C + (size_t)blockIdx.z * MM * N;

    auto load_stage = [&](int c, int s) {
        const uint32_t base = sb + s * GSTAGE;
        const int k0 = kbase + c * 64;
#pragma unroll
        for (int i = 0; i < 24; i++) {
            int idx = i * 256 + tid;
            const __nv_bfloat16* src;
            uint32_t dst;
            if (idx < 4096) {
                int arr = idx >> 11;
                int j = idx & 2047;
                int r = j >> 3, q = j & 7;
                dst = base + arr * GA_ARR + r * GRS + q * 16;
                src = (arr == 0 ? Ah : Al) + (size_t)(m0 + r) * K + k0 + q * 8;
            } else {
                int j = idx - 4096;
                int arr = j >> 10;
                int jj = j & 1023;
                int r = jj >> 3, q = jj & 7;
                dst = base + 2 * GA_ARR + arr * GW_ARR + r * GRS + q * 16;
                src = (arr == 0 ? Wh : Wl) + (size_t)(n0 + r) * K + k0 + q * 8;
            }
            CP16(dst, src);
        }
    };

    float acc[4][8][4];
#pragma unroll
    for (int i = 0; i < 4; i++)
#pragma unroll
        for (int j = 0; j < 8; j++)
#pragma unroll
            for (int k = 0; k < 4; k++) acc[i][j][k] = 0.0f;

    load_stage(0, 0);
    CP_COMMIT();

    const int sub = lane >> 3;
    const int r8 = lane & 7;
    const uint32_t a_base = (uint32_t)((wm * 64 + r8 + (sub & 1) * 8) * GRS + (sub >> 1) * 16);
    const uint32_t b_base = (uint32_t)((wn * 64 + (sub >> 1) * 8 + r8) * GRS + (sub & 1) * 16);

    for (int c = 0; c < nchunks; c++) {
        const int s = c & 1;
        CP_WAIT(0);
        __syncthreads();
        if (c + 1 < nchunks) {
            load_stage(c + 1, s ^ 1);
            CP_COMMIT();
        }
        const uint32_t stb = sb + s * GSTAGE;
#pragma unroll
        for (int kf = 0; kf < 4; kf++) {
            uint32_t ah[4][4], al[4][4];
#pragma unroll
            for (int mf = 0; mf < 4; mf++) {
                uint32_t off = a_base + mf * 16 * GRS + kf * 32;
                ldm4(ah[mf], stb + off);
                ldm4(al[mf], stb + GA_ARR + off);
            }
            uint32_t bh[8][2], bl[8][2];
#pragma unroll
            for (int nt2 = 0; nt2 < 4; nt2++) {
                uint32_t off = b_base + nt2 * 16 * GRS + kf * 32;
                uint32_t r[4];
                ldm4(r, stb + 2 * GA_ARR + off);
                bh[nt2 * 2][0] = r[0]; bh[nt2 * 2][1] = r[1];
                bh[nt2 * 2 + 1][0] = r[2]; bh[nt2 * 2 + 1][1] = r[3];
                ldm4(r, stb + 2 * GA_ARR + GW_ARR + off);
                bl[nt2 * 2][0] = r[0]; bl[nt2 * 2][1] = r[1];
                bl[nt2 * 2 + 1][0] = r[2]; bl[nt2 * 2 + 1][1] = r[3];
            }
#pragma unroll
            for (int mf = 0; mf < 4; mf++)
#pragma unroll
                for (int nf = 0; nf < 8; nf++) mma_bf16(acc[mf][nf], ah[mf], bh[nf]);
#pragma unroll
            for (int mf = 0; mf < 4; mf++)
#pragma unroll
                for (int nf = 0; nf < 8; nf++) mma_bf16(acc[mf][nf], al[mf], bh[nf]);
#pragma unroll
            for (int mf = 0; mf < 4; mf++)
#pragma unroll
                for (int nf = 0; nf < 8; nf++) mma_bf16(acc[mf][nf], ah[mf], bl[nf]);
        }
    }

    const int g = lane >> 2;
    const int tg = lane & 3;
    const bool addb = (blockIdx.z == 0);
#pragma unroll
    for (int mf = 0; mf < 4; mf++) {
#pragma unroll
        for (int nf = 0; nf < 8; nf++) {
            int row = m0 + wm * 64 + mf * 16 + g;
            int col = n0 + wn * 64 + nf * 8 + tg * 2;
            float b0 = addb ? bias[col] : 0.0f;
            float b1 = addb ? bias[col + 1] : 0.0f;
            float v0 = acc[mf][nf][0] + b0;
            float v1 = acc[mf][nf][1] + b1;
            float v2 = acc[mf][nf][2] + b0;
            float v3 = acc[mf][nf][3] + b1;
            if (mode != 0) {
                if (mode == 1) {
                    v0 = gelu_tanh(v0); v1 = gelu_tanh(v1);
                    v2 = gelu_tanh(v2); v3 = gelu_tanh(v3);
                }
                size_t o0 = (size_t)row * N + col;
                size_t o1 = (size_t)(row + 8) * N + col;
                split2(v0, v1, Ch + o0, Cl + o0);
                split2(v2, v3, Ch + o1, Cl + o1);
            } else {
                *(float2*)&Cz[(size_t)row * N + col] = make_float2(v0, v1);
                *(float2*)&Cz[(size_t)(row + 8) * N + col] = make_float2(v2, v3);
            }
        }
    }
}

// ---------------- fused flash attention (bf16 hi/lo inputs via cp.async) ----
#define FRS 144
#define FT (128 * FRS)
#define FLASH_SMEM (4 * FT + 512)

__global__ void __launch_bounds__(256, 1) flash_attn(
    const __nv_bfloat16* __restrict__ Qh, const __nv_bfloat16* __restrict__ Ql,
    const int* __restrict__ mask,
    __nv_bfloat16* __restrict__ Oh, __nv_bfloat16* __restrict__ Ol) {
    extern __shared__ __align__(128) char smem[];
    const uint32_t sb = smem_u32(smem);
    float* am_sm = (float*)(smem + 4 * FT);

    const int tid = threadIdx.x;
    const int wid = tid >> 5;
    const int lane = tid & 31;
    const int sub = lane >> 3, r8 = lane & 7;
    const int g = lane >> 2, tg = lane & 3;
    const int bz = blockIdx.y;
    const int b = bz / HH, h = bz % HH;
    const int m0 = (gridDim.x - 1 - blockIdx.x) * 128;

    // bf16 qkv layout: [M, QD]; Q at col h*DH, K at DD+h*DH, V at 2DD+h*DH
    const size_t rowbase = (size_t)(b * SS);

    // ---- stage Q tiles (hi,lo) via cp.async ----
#pragma unroll
    for (int i = 0; i < 8; i++) {
        int idx = i * 256 + tid;
        int arr = idx >> 10;             // 0: hi, 1: lo
        int j = idx & 1023;
        int r = j >> 3, q = j & 7;
        uint32_t dst = sb + arr * FT + r * FRS + q * 16;
        const __nv_bfloat16* src = (arr == 0 ? Qh : Ql)
            + (rowbase + m0 + r) * QD + h * DH + q * 8;
        CP16(dst, src);
    }
    CP_COMMIT();
    CP_WAIT(0);
    __syncthreads();
    uint32_t qh[4][4], ql[4][4];
#pragma unroll
    for (int kf = 0; kf < 4; kf++) {
        uint32_t off = (uint32_t)((wid * 16 + r8 + (sub & 1) * 8) * FRS + kf * 32 + (sub >> 1) * 16);
        ldm4(qh[kf], sb + off);
        ldm4(ql[kf], sb + FT + off);
    }

    float mprev0 = -1e30f, mprev1 = -1e30f;
    float l0 = 0.0f, l1 = 0.0f;
    float acco[8][4];
#pragma unroll
    for (int j = 0; j < 8; j++)
#pragma unroll
        for (int k = 0; k < 4; k++) acco[j][k] = 0.0f;

    const int nch = (m0 >> 7) + 1;
    const int rowg = m0 + wid * 16 + g;

    for (int kc = 0; kc < nch; kc++) {
        const int k0 = kc * 128;
        __syncthreads();   // previous chunk (and Q tiles) fully consumed
        // ---- stage K,V (hi,lo) via cp.async: 4 arrays x 128 rows x 8 chunks ----
#pragma unroll
        for (int i = 0; i < 16; i++) {
            int idx = i * 256 + tid;
            int arr = idx >> 10;         // 0:Kh 1:Kl 2:Vh 3:Vl
            int j = idx & 1023;
            int r = j >> 3, q = j & 7;
            uint32_t dst = sb + arr * FT + r * FRS + q * 16;
            const __nv_bfloat16* base =
                (arr == 0) ? Qh : (arr == 1) ? Ql : (arr == 2) ? Qh : Ql;
            int colofs = (arr < 2) ? (DD + h * DH) : (2 * DD + h * DH);
            CP16(dst, base + (rowbase + k0 + r) * QD + colofs + q * 8);
        }
        CP_COMMIT();
        if (tid < 128) am_sm[tid] = (1.0f - (float)mask[b * SS + k0 + tid]) * -10000.0f;
        CP_WAIT(0);
        __syncthreads();

        float sacc[16][4];
#pragma unroll
        for (int j = 0; j < 16; j++)
#pragma unroll
            for (int k = 0; k < 4; k++) sacc[j][k] = 0.0f;

#pragma unroll
        for (int nq = 0; nq < 4; nq++) {
#pragma unroll
            for (int kfp = 0; kfp < 2; kfp++) {
                uint32_t kbh[2][4][2], kbl[2][4][2];
#pragma unroll
                for (int kf2 = 0; kf2 < 2; kf2++) {
                    int kf = kfp * 2 + kf2;
#pragma unroll
                    for (int j = 0; j < 2; j++) {
                        uint32_t off = (uint32_t)((nq * 32 + j * 16 + (sub >> 1) * 8 + r8) * FRS
                                                  + kf * 32 + (sub & 1) * 16);
                        uint32_t r[4];
                        ldm4(r, sb + off);
                        kbh[kf2][j * 2][0] = r[0]; kbh[kf2][j * 2][1] = r[1];
                        kbh[kf2][j * 2 + 1][0] = r[2]; kbh[kf2][j * 2 + 1][1] = r[3];
                        ldm4(r, sb + FT + off);
                        kbl[kf2][j * 2][0] = r[0]; kbl[kf2][j * 2][1] = r[1];
                        kbl[kf2][j * 2 + 1][0] = r[2]; kbl[kf2][j * 2 + 1][1] = r[3];
                    }
                }
#pragma unroll
                for (int kf2 = 0; kf2 < 2; kf2++)
#pragma unroll
                    for (int t = 0; t < 4; t++)
                        mma_bf16(sacc[nq * 4 + t], qh[kfp * 2 + kf2], kbh[kf2][t]);
#pragma unroll
                for (int kf2 = 0; kf2 < 2; kf2++)
#pragma unroll
                    for (int t = 0; t < 4; t++)
                        mma_bf16(sacc[nq * 4 + t], ql[kfp * 2 + kf2], kbh[kf2][t]);
#pragma unroll
                for (int kf2 = 0; kf2 < 2; kf2++)
#pragma unroll
                    for (int t = 0; t < 4; t++)
                        mma_bf16(sacc[nq * 4 + t], qh[kfp * 2 + kf2], kbl[kf2][t]);
            }
        }

        const bool diag = (kc == (m0 >> 7));
        float mx0 = -1e30f, mx1 = -1e30f;
#pragma unroll
        for (int nf = 0; nf < 16; nf++) {
            int cl = nf * 8 + tg * 2;
            float am0 = am_sm[cl], am1 = am_sm[cl + 1];
            float v0 = sacc[nf][0] * 0.125f + am0;
            float v1 = sacc[nf][1] * 0.125f + am1;
            float v2 = sacc[nf][2] * 0.125f + am0;
            float v3 = sacc[nf][3] * 0.125f + am1;
            if (diag) {
                int col = k0 + cl;
                if (col > rowg)         v0 = -10000.0f + am0;
                if (col + 1 > rowg)     v1 = -10000.0f + am1;
                if (col > rowg + 8)     v2 = -10000.0f + am0;
                if (col + 1 > rowg + 8) v3 = -10000.0f + am1;
            }
            sacc[nf][0] = v0; sacc[nf][1] = v1; sacc[nf][2] = v2; sacc[nf][3] = v3;
            mx0 = fmaxf(mx0, fmaxf(v0, v1));
            mx1 = fmaxf(mx1, fmaxf(v2, v3));
        }
        mx0 = fmaxf(mx0, __shfl_xor_sync(0xffffffffu, mx0, 1));
        mx0 = fmaxf(mx0, __shfl_xor_sync(0xffffffffu, mx0, 2));
        mx1 = fmaxf(mx1, __shfl_xor_sync(0xffffffffu, mx1, 1));
        mx1 = fmaxf(mx1, __shfl_xor_sync(0xffffffffu, mx1, 2));
        float mnew0 = fmaxf(mprev0, mx0), mnew1 = fmaxf(mprev1, mx1);
        float corr0 = __expf(mprev0 - mnew0), corr1 = __expf(mprev1 - mnew1);
        mprev0 = mnew0; mprev1 = mnew1;
        l0 *= corr0; l1 *= corr1;
#pragma unroll
        for (int nf2 = 0; nf2 < 8; nf2++) {
            acco[nf2][0] *= corr0; acco[nf2][1] *= corr0;
            acco[nf2][2] *= corr1; acco[nf2][3] *= corr1;
        }

        float ps0 = 0.0f, ps1 = 0.0f;
#pragma unroll
        for (int kt = 0; kt < 8; kt++) {
            float p00 = __expf(sacc[2 * kt][0] - mnew0);
            float p01 = __expf(sacc[2 * kt][1] - mnew0);
            float p02 = __expf(sacc[2 * kt][2] - mnew1);
            float p03 = __expf(sacc[2 * kt][3] - mnew1);
            float p10 = __expf(sacc[2 * kt + 1][0] - mnew0);
            float p11 = __expf(sacc[2 * kt + 1][1] - mnew0);
            float p12 = __expf(sacc[2 * kt + 1][2] - mnew1);
            float p13 = __expf(sacc[2 * kt + 1][3] - mnew1);
            ps0 += p00 + p01 + p10 + p11;
            ps1 += p02 + p03 + p12 + p13;
            uint32_t aph[4], apl[4];
            pack2(p00, p01, &aph[0], &apl[0]);
            pack2(p02, p03, &aph[1], &apl[1]);
            pack2(p10, p11, &aph[2], &apl[2]);
            pack2(p12, p13, &aph[3], &apl[3]);

            uint32_t vh[8][2], vl[8][2];
#pragma unroll
            for (int nt2 = 0; nt2 < 4; nt2++) {
                uint32_t off = (uint32_t)((kt * 16 + (sub & 1) * 8 + r8) * FRS
                                          + (nt2 * 16 + (sub >> 1) * 8) * 2);
                uint32_t r[4];
                ldm4t(r, sb + 2 * FT + off);
                vh[nt2 * 2][0] = r[0]; vh[nt2 * 2][1] = r[1];
                vh[nt2 * 2 + 1][0] = r[2]; vh[nt2 * 2 + 1][1] = r[3];
                ldm4t(r, sb + 3 * FT + off);
                vl[nt2 * 2][0] = r[0]; vl[nt2 * 2][1] = r[1];
                vl[nt2 * 2 + 1][0] = r[2]; vl[nt2 * 2 + 1][1] = r[3];
            }
#pragma unroll
            for (int nf2 = 0; nf2 < 8; nf2++) mma_bf16(acco[nf2], aph, vh[nf2]);
#pragma unroll
            for (int nf2 = 0; nf2 < 8; nf2++) mma_bf16(acco[nf2], apl, vh[nf2]);
#pragma unroll
            for (int nf2 = 0; nf2 < 8; nf2++) mma_bf16(acco[nf2], aph, vl[nf2]);
        }
        ps0 += __shfl_xor_sync(0xffffffffu, ps0, 1);
        ps0 += __shfl_xor_sync(0xffffffffu, ps0, 2);
        ps1 += __shfl_xor_sync(0xffffffffu, ps1, 1);
        ps1 += __shfl_xor_sync(0xffffffffu, ps1, 2);
        l0 += ps0; l1 += ps1;
    }

    float inv0 = 1.0f / l0, inv1 = 1.0f / l1;
#pragma unroll
    for (int nf2 = 0; nf2 < 8; nf2++) {
        int col = h * DH + nf2 * 8 + tg * 2;
        int row0 = m0 + wid * 16 + g;
        size_t o0 = (rowbase + row0) * DD + col;
        size_t o1 = o0 + 8 * DD;
        split2(acco[nf2][0] * inv0, acco[nf2][1] * inv0, Oh + o0, Ol + o0);
        split2(acco[nf2][2] * inv1, acco[nf2][3] * inv1, Oh + o1, Ol + o1);
    }
}

// ---------------- residual add (3 partials) + LayerNorm (+ bf16 split) ------
__global__ __launch_bounds__(256) void add_ln(
    const float* __restrict__ x, const float* __restrict__ y0,
    const float* __restrict__ y1, const float* __restrict__ y2,
    const float* __restrict__ g, const float* __restrict__ b,
    float* __restrict__ out, __nv_bfloat16* __restrict__ hi,
    __nv_bfloat16* __restrict__ lo, int do_split) {
    __shared__ float sh[8];
    int row = blockIdx.x;
    int t = threadIdx.x;
    const float* xp = x + (size_t)row * DD;
    const float* y0p = y0 + (size_t)row * DD;
    const float* y1p = y1 + (size_t)row * DD;
    const float* y2p = y2 + (size_t)row * DD;
    float s[3];
    float loc = 0.0f;
#pragma unroll
    for (int i = 0; i < 3; i++) {
        int c = t + 256 * i;
        s[i] = xp[c] + (y0p[c] + y1p[c] + y2p[c]);
        loc += s[i];
    }
    float mean = block_sum<8>(loc, sh) * (1.0f / DD);
    float loc2 = 0.0f;
#pragma unroll
    for (int i = 0; i < 3; i++) {
        float d = s[i] - mean;
        loc2 += d * d;
    }
    float var = block_sum<8>(loc2, sh) * (1.0f / DD);
    float inv = rsqrtf(var + 1e-5f);
    float* op = out + (size_t)row * DD;
#pragma unroll
    for (int i = 0; i < 3; i++) {
        int c = t + 256 * i;
        float v = (s[i] - mean) * inv * g[c] + b[c];
        op[c] = v;
        if (do_split) {
            size_t o = (size_t)row * DD + c;
            __nv_bfloat16 hh = __float2bfloat16(v);
            hi[o] = hh;
            lo[o] = __float2bfloat16(v - __bfloat162float(hh));
        }
    }
}

// ---------------------------------------------------------------------------
extern "C" void kernel_launch(void* const* d_in, const int* in_sizes, int n_in,
                              void* d_out, int out_size) {
    const int* ids = (const int*)d_in[0];
    const int* amask = (const int*)d_in[1];
    const float* tok = (const float*)d_in[2];
    const float* pos = (const float*)d_in[3];
    const float* Wqkv = (const float*)d_in[4];
    const float* bqkv = (const float*)d_in[5];
    const float* Wo = (const float*)d_in[6];
    const float* bo = (const float*)d_in[7];
    const float* g1 = (const float*)d_in[8];
    const float* b1 = (const float*)d_in[9];
    const float* Wfc = (const float*)d_in[10];
    const float* bfc = (const float*)d_in[11];
    const float* Wp2 = (const float*)d_in[12];
    const float* bp2 = (const float*)d_in[13];
    const float* g2 = (const float*)d_in[14];
    const float* b2 = (const float*)d_in[15];
    float* out = (float*)d_out;

    float *h, *n, *qkv;
    __nv_bfloat16 *Ah, *Al, *Fh, *Fl;
    __nv_bfloat16 *Wqkv_h, *Wqkv_l, *Wo_h, *Wo_l, *Wfc_h, *Wfc_l, *Wp2_h, *Wp2_l;
    cudaGetSymbolAddress((void**)&h, g_h);
    cudaGetSymbolAddress((void**)&n, g_n);
    cudaGetSymbolAddress((void**)&qkv, g_qkv);
    cudaGetSymbolAddress((void**)&Ah, g_Ah);
    cudaGetSymbolAddress((void**)&Al, g_Al);
    cudaGetSymbolAddress((void**)&Fh, g_Fh);
    cudaGetSymbolAddress((void**)&Fl, g_Fl);
    cudaGetSymbolAddress((void**)&Wqkv_h, g_Wqkv_h);
    cudaGetSymbolAddress((void**)&Wqkv_l, g_Wqkv_l);
    cudaGetSymbolAddress((void**)&Wo_h, g_Wo_h);
    cudaGetSymbolAddress((void**)&Wo_l, g_Wo_l);
    cudaGetSymbolAddress((void**)&Wfc_h, g_Wfc_h);
    cudaGetSymbolAddress((void**)&Wfc_l, g_Wfc_l);
    cudaGetSymbolAddress((void**)&Wp2_h, g_Wp2_h);
    cudaGetSymbolAddress((void**)&Wp2_l, g_Wp2_l);

    float* q1 = qkv + (size_t)MM * DD;
    float* q2 = qkv + (size_t)2 * MM * DD;

    cudaFuncSetAttribute(gemm_mma, cudaFuncAttributeMaxDynamicSharedMemorySize, GEMM_SMEM);
    cudaFuncSetAttribute(flash_attn, cudaFuncAttributeMaxDynamicSharedMemorySize, FLASH_SMEM);

    // ---- hoisted: all 12 layers' weight transpose+split ----
    conv_wT<<<dim3((3 * DD) / 32, DD / 32, LL), 256>>>(Wqkv, Wqkv_h, Wqkv_l, DD, 3 * DD);
    conv_wT<<<dim3(DD / 32, DD / 32, LL), 256>>>(Wo, Wo_h, Wo_l, DD, DD);
    conv_wT<<<dim3(FF / 32, DD / 32, LL), 256>>>(Wfc, Wfc_h, Wfc_l, DD, FF);
    conv_wT<<<dim3(DD / 32, FF / 32, LL), 256>>>(Wp2, Wp2_h, Wp2_l, FF, DD);

    embed_kernel<<<(MM * DD / 2 + 255) / 256, 256>>>(ids, tok, pos, h, Ah, Al);

    for (int l = 0; l < LL; l++) {
        const float* bqkv_l = bqkv + (size_t)l * 3 * DD;
        const float* bo_l = bo + (size_t)l * DD;
        const float* bfc_l = bfc + (size_t)l * FF;
        const float* bp2_l = bp2 + (size_t)l * DD;
        const __nv_bfloat16* Wqh = Wqkv_h + (size_t)l * 3 * DD * DD;
        const __nv_bfloat16* Wql = Wqkv_l + (size_t)l * 3 * DD * DD;
        const __nv_bfloat16* Woh = Wo_h + (size_t)l * DD * DD;
        const __nv_bfloat16* Wol = Wo_l + (size_t)l * DD * DD;
        const __nv_bfloat16* Wfh = Wfc_h + (size_t)l * FF * DD;
        const __nv_bfloat16* Wfl = Wfc_l + (size_t)l * FF * DD;
        const __nv_bfloat16* Wph = Wp2_h + (size_t)l * DD * FF;
        const __nv_bfloat16* Wpl = Wp2_l + (size_t)l * DD * FF;

        // ---- qkv = h @ Wqkv + bqkv -> bf16 hi/lo in Fh/Fl [M, 2304] ----
        gemm_mma<<<dim3((3 * DD) / 128, MM / 256, 1), 256, GEMM_SMEM>>>(
            Ah, Al, Wqh, Wql, bqkv_l, nullptr, Fh, Fl, 3 * DD, DD, 2);

        // ---- fused attention (bf16 in) -> a (bf16 hi/lo) ----
        flash_attn<<<dim3(SS / 128, BH), 256, FLASH_SMEM>>>(Fh, Fl, amask, Ah, Al);

        // ---- o-proj: split-K=3 (288 CTAs), fp32 partials ----
        gemm_mma<<<dim3(DD / 128, MM / 256, 3), 256, GEMM_SMEM>>>(
            Ah, Al, Woh, Wol, bo_l, qkv, nullptr, nullptr, DD, DD, 0);
        add_ln<<<MM, 256>>>(h, qkv, q1, q2, g1 + (size_t)l * DD, b1 + (size_t)l * DD,
                            n, Ah, Al, 1);

        // ---- MLP ----
        gemm_mma<<<dim3(FF / 128, MM / 256, 1), 256, GEMM_SMEM>>>(
            Ah, Al, Wfh, Wfl, bfc_l, nullptr, Fh, Fl, FF, DD, 1);

        gemm_mma<<<dim3(DD / 128, MM / 256, 3), 256, GEMM_SMEM>>>(
            Fh, Fl, Wph, Wpl, bp2_l, qkv, nullptr, nullptr, DD, FF, 0);

        float* dst = (l == LL - 1) ? out : h;
        add_ln<<<MM, 256>>>(n, qkv, q1, q2, g2 + (size_t)l * DD, b2 + (size_t)l * DD,
                            dst, Ah, Al, (l == LL - 1) ? 0 : 1);
    }
}

// round 17
// speedup vs baseline: 1.0211x; 1.0211x over previous
#include <cuda_runtime.h>
#include <cuda_bf16.h>
#include <math.h>
#include <stdint.h>

// ---------------------------------------------------------------------------
// GPT forward: B=8, S=512, D=768, H=12, dh=64, L=12, FF=3072, M = 4096
// GEMMs on mma.sync bf16 (3-term hi/lo split, 256x128 CTA tile, BK=64,
// double-buffered, split-K for narrow GEMMs); flash attention fused;
// weight conversion hoisted; HW tanh.approx gelu; vectorized add_ln.
// ---------------------------------------------------------------------------
#define BB 8
#define SS 512
#define DD 768
#define HH 12
#define DH 64
#define LL 12
#define FF 3072
#define MM (BB * SS)       // 4096
#define BH (BB * HH)       // 96

// ---------------- scratch (static device globals; no allocation) -----------
__device__ float g_h[MM * DD];
__device__ float g_n[MM * DD];
__device__ float g_qkv[MM * 3 * DD];   // qkv OR 3 split-K partials of [MM,DD]
__device__ __nv_bfloat16 g_Ah[(size_t)MM * DD];
__device__ __nv_bfloat16 g_Al[(size_t)MM * DD];
__device__ __nv_bfloat16 g_Fh[(size_t)MM * FF];
__device__ __nv_bfloat16 g_Fl[(size_t)MM * FF];
// all-layer split weights, transposed [N,K]
__device__ __nv_bfloat16 g_Wqkv_h[(size_t)LL * 3 * DD * DD];
__device__ __nv_bfloat16 g_Wqkv_l[(size_t)LL * 3 * DD * DD];
__device__ __nv_bfloat16 g_Wo_h[(size_t)LL * DD * DD];
__device__ __nv_bfloat16 g_Wo_l[(size_t)LL * DD * DD];
__device__ __nv_bfloat16 g_Wfc_h[(size_t)LL * FF * DD];
__device__ __nv_bfloat16 g_Wfc_l[(size_t)LL * FF * DD];
__device__ __nv_bfloat16 g_Wp2_h[(size_t)LL * DD * FF];
__device__ __nv_bfloat16 g_Wp2_l[(size_t)LL * DD * FF];

// ---------------- helpers ----------------------------------------------------
__device__ __forceinline__ uint32_t smem_u32(const void* p) {
    uint32_t a;
    asm("{ .reg .u64 t; cvta.to.shared.u64 t, %1; cvt.u32.u64 %0, t; }" : "=r"(a) : "l"(p));
    return a;
}
#define CP16(dst, src) asm volatile("cp.async.cg.shared.global [%0], [%1], 16;" :: "r"((uint32_t)(dst)), "l"(src) : "memory")
#define CP_COMMIT()    asm volatile("cp.async.commit_group;" ::: "memory")
#define CP_WAIT(n)     asm volatile("cp.async.wait_group %0;" :: "n"(n) : "memory")

__device__ __forceinline__ void ldm4(uint32_t* r, uint32_t addr) {
    asm volatile("ldmatrix.sync.aligned.m8n8.x4.shared.b16 {%0,%1,%2,%3}, [%4];"
                 : "=r"(r[0]), "=r"(r[1]), "=r"(r[2]), "=r"(r[3]) : "r"(addr));
}
__device__ __forceinline__ void ldm4t(uint32_t* r, uint32_t addr) {
    asm volatile("ldmatrix.sync.aligned.m8n8.x4.trans.shared.b16 {%0,%1,%2,%3}, [%4];"
                 : "=r"(r[0]), "=r"(r[1]), "=r"(r[2]), "=r"(r[3]) : "r"(addr));
}
__device__ __forceinline__ void mma_bf16(float* c, const uint32_t* a, const uint32_t* b) {
    asm volatile(
        "mma.sync.aligned.m16n8k16.row.col.f32.bf16.bf16.f32 "
        "{%0,%1,%2,%3}, {%4,%5,%6,%7}, {%8,%9}, {%0,%1,%2,%3};"
        : "+f"(c[0]), "+f"(c[1]), "+f"(c[2]), "+f"(c[3])
        : "r"(a[0]), "r"(a[1]), "r"(a[2]), "r"(a[3]), "r"(b[0]), "r"(b[1]));
}

__device__ __forceinline__ float tanh_fast(float x) {
    float r;
    asm("tanh.approx.f32 %0, %1;" : "=f"(r) : "f"(x));
    return r;
}
__device__ __forceinline__ float gelu_tanh(float x) {
    float x3 = x * x * x;
    return 0.5f * x * (1.0f + tanh_fast(0.7978845608028654f * (x + 0.044715f * x3)));
}
__device__ __forceinline__ void split2(float x, float y, __nv_bfloat16* hi, __nv_bfloat16* lo) {
    __nv_bfloat16 h0 = __float2bfloat16(x), h1 = __float2bfloat16(y);
    *(__nv_bfloat162*)hi = __nv_bfloat162(h0, h1);
    *(__nv_bfloat162*)lo = __nv_bfloat162(__float2bfloat16(x - __bfloat162float(h0)),
                                          __float2bfloat16(y - __bfloat162float(h1)));
}
__device__ __forceinline__ void pack2(float x, float y, uint32_t* hi, uint32_t* lo) {
    __nv_bfloat162 h(__float2bfloat16(x), __float2bfloat16(y));
    *hi = *(uint32_t*)&h;
    __nv_bfloat162 l(__float2bfloat16(x - __bfloat162float(h.x)),
                     __float2bfloat16(y - __bfloat162float(h.y)));
    *lo = *(uint32_t*)&l;
}

template <int WARPS>
__device__ __forceinline__ float block_sum(float v, float* sh) {
    int t = threadIdx.x;
#pragma unroll
    for (int o = 16; o > 0; o >>= 1) v += __shfl_xor_sync(0xffffffffu, v, o);
    if ((t & 31) == 0) sh[t >> 5] = v;
    __syncthreads();
    if (t == 0) {
        float s = sh[0];
#pragma unroll
        for (int w = 1; w < WARPS; w++) s += sh[w];
        sh[0] = s;
    }
    __syncthreads();
    float r = sh[0];
    __syncthreads();
    return r;
}

// ---------------- embedding (+ bf16 split) ----------------------------------
__global__ __launch_bounds__(256) void embed_kernel(
    const int* __restrict__ ids, const float* __restrict__ tok,
    const float* __restrict__ pos, float* __restrict__ h,
    __nv_bfloat16* __restrict__ hi, __nv_bfloat16* __restrict__ lo) {
    int i = (blockIdx.x * 256 + threadIdx.x) * 2;
    if (i >= MM * DD) return;
    int row = i / DD;
    int c = i - row * DD;
    int s = row & (SS - 1);
    size_t tb = (size_t)ids[row] * DD + c;
    size_t pb = (size_t)s * DD + c;
    float v0 = tok[tb] + pos[pb];
    float v1 = tok[tb + 1] + pos[pb + 1];
    h[i] = v0; h[i + 1] = v1;
    split2(v0, v1, hi + i, lo + i);
}

// ---------------- weight transpose+split (all layers): W[l][K,N] -> [l][N,K]
__global__ __launch_bounds__(256) void conv_wT(
    const float* __restrict__ W, __nv_bfloat16* __restrict__ Whi,
    __nv_bfloat16* __restrict__ Wlo, int K, int N) {
    __shared__ float t[32][33];
    int tx = threadIdx.x & 31;
    int ty = threadIdx.x >> 5;
    int bx = blockIdx.x;
    int by = blockIdx.y;
    size_t lofs = (size_t)blockIdx.z * K * N;
    const float* Wl_ = W + lofs;
    __nv_bfloat16* Hh = Whi + lofs;
    __nv_bfloat16* Hl = Wlo + lofs;
#pragma unroll
    for (int i = 0; i < 4; i++)
        t[ty + i * 8][tx] = Wl_[(size_t)(by * 32 + ty + i * 8) * N + bx * 32 + tx];
    __syncthreads();
    const int kk = (threadIdx.x & 15) * 2;
    const int nn0 = threadIdx.x >> 4;
#pragma unroll
    for (int i = 0; i < 2; i++) {
        int nn = nn0 + i * 16;
        float v0 = t[kk][nn];
        float v1 = t[kk + 1][nn];
        uint32_t uh, ul;
        pack2(v0, v1, &uh, &ul);
        size_t idx = (size_t)(bx * 32 + nn) * K + by * 32 + kk;
        *(uint32_t*)&Hh[idx] = uh;
        *(uint32_t*)&Hl[idx] = ul;
    }
}

// ---------------- bf16 mma.sync GEMM: C = A[M,K] @ Wt[N,K]^T + bias ---------
// CTA 256(M)x128(N), BK=64, 8 warps (4M x 2N), warp tile 64x64, double buffer.
// Split-K via gridDim.z: slice z covers K-range z*K/ks.., writes C + z*MM*N.
#define GRS 144
#define GA_ARR (256 * GRS)
#define GW_ARR (128 * GRS)
#define GSTAGE (2 * GA_ARR + 2 * GW_ARR)   // 110592
#define GEMM_SMEM (2 * GSTAGE)             // 221184

__global__ void __launch_bounds__(256, 1) gemm_mma(
    const __nv_bfloat16* __restrict__ Ah, const __nv_bfloat16* __restrict__ Al,
    const __nv_bfloat16* __restrict__ Wh, const __nv_bfloat16* __restrict__ Wl,
    const float* __restrict__ bias, float* __restrict__ C,
    __nv_bfloat16* __restrict__ Ch, __nv_bfloat16* __restrict__ Cl,
    int N, int K, int mode) {
    extern __shared__ __align__(128) char smem[];
    const uint32_t sb = smem_u32(smem);

    const int tid = threadIdx.x;
    const int wid = tid >> 5;
    const int lane = tid & 31;
    const int wm = wid & 3;
    const int wn = wid >> 2;
    const int m0 = blockIdx.y * 256;
    const int n0 = blockIdx.x * 128;
    const int ksl = K / gridDim.z;
    const int kbase = blockIdx.z * ksl;
    const int nchunks = ksl >> 6;
    float* Cz = C + (size_t)blockIdx.z * MM * N;

    auto load_stage = [&](int c, int s) {
        const uint32_t base = sb + s * GSTAGE;
        const int k0 = kbase + c * 64;
#pragma unroll
        for (int i = 0; i < 24; i++) {
            int idx = i * 256 + tid;
            const __nv_bfloat16* src;
            uint32_t dst;
            if (idx < 4096) {
                int arr = idx >> 11;
                int j = idx & 2047;
                int r = j >> 3, q = j & 7;
                dst = base + arr * GA_ARR + r * GRS + q * 16;
                src = (arr == 0 ? Ah : Al) + (size_t)(m0 + r) * K + k0 + q * 8;
            } else {
                int j = idx - 4096;
                int arr = j >> 10;
                int jj = j & 1023;
                int r = jj >> 3, q = jj & 7;
                dst = base + 2 * GA_ARR + arr * GW_ARR + r * GRS + q * 16;
                src = (arr == 0 ? Wh : Wl) + (size_t)(n0 + r) * K + k0 + q * 8;
            }
            CP16(dst, src);
        }
    };

    float acc[4][8][4];
#pragma unroll
    for (int i = 0; i < 4; i++)
#pragma unroll
        for (int j = 0; j < 8; j++)
#pragma unroll
            for (int k = 0; k < 4; k++) acc[i][j][k] = 0.0f;

    load_stage(0, 0);
    CP_COMMIT();

    const int sub = lane >> 3;
    const int r8 = lane & 7;
    const uint32_t a_base = (uint32_t)((wm * 64 + r8 + (sub & 1) * 8) * GRS + (sub >> 1) * 16);
    const uint32_t b_base = (uint32_t)((wn * 64 + (sub >> 1) * 8 + r8) * GRS + (sub & 1) * 16);

    for (int c = 0; c < nchunks; c++) {
        const int s = c & 1;
        CP_WAIT(0);
        __syncthreads();
        if (c + 1 < nchunks) {
            load_stage(c + 1, s ^ 1);
            CP_COMMIT();
        }
        const uint32_t stb = sb + s * GSTAGE;
#pragma unroll
        for (int kf = 0; kf < 4; kf++) {
            uint32_t ah[4][4], al[4][4];
#pragma unroll
            for (int mf = 0; mf < 4; mf++) {
                uint32_t off = a_base + mf * 16 * GRS + kf * 32;
                ldm4(ah[mf], stb + off);
                ldm4(al[mf], stb + GA_ARR + off);
            }
            uint32_t bh[8][2], bl[8][2];
#pragma unroll
            for (int nt2 = 0; nt2 < 4; nt2++) {
                uint32_t off = b_base + nt2 * 16 * GRS + kf * 32;
                uint32_t r[4];
                ldm4(r, stb + 2 * GA_ARR + off);
                bh[nt2 * 2][0] = r[0]; bh[nt2 * 2][1] = r[1];
                bh[nt2 * 2 + 1][0] = r[2]; bh[nt2 * 2 + 1][1] = r[3];
                ldm4(r, stb + 2 * GA_ARR + GW_ARR + off);
                bl[nt2 * 2][0] = r[0]; bl[nt2 * 2][1] = r[1];
                bl[nt2 * 2 + 1][0] = r[2]; bl[nt2 * 2 + 1][1] = r[3];
            }
#pragma unroll
            for (int mf = 0; mf < 4; mf++)
#pragma unroll
                for (int nf = 0; nf < 8; nf++) mma_bf16(acc[mf][nf], ah[mf], bh[nf]);
#pragma unroll
            for (int mf = 0; mf < 4; mf++)
#pragma unroll
                for (int nf = 0; nf < 8; nf++) mma_bf16(acc[mf][nf], al[mf], bh[nf]);
#pragma unroll
            for (int mf = 0; mf < 4; mf++)
#pragma unroll
                for (int nf = 0; nf < 8; nf++) mma_bf16(acc[mf][nf], ah[mf], bl[nf]);
        }
    }

    const int g = lane >> 2;
    const int tg = lane & 3;
    const bool addb = (blockIdx.z == 0);
#pragma unroll
    for (int mf = 0; mf < 4; mf++) {
#pragma unroll
        for (int nf = 0; nf < 8; nf++) {
            int row = m0 + wm * 64 + mf * 16 + g;
            int col = n0 + wn * 64 + nf * 8 + tg * 2;
            float b0 = addb ? bias[col] : 0.0f;
            float b1 = addb ? bias[col + 1] : 0.0f;
            float v0 = acc[mf][nf][0] + b0;
            float v1 = acc[mf][nf][1] + b1;
            float v2 = acc[mf][nf][2] + b0;
            float v3 = acc[mf][nf][3] + b1;
            if (mode == 1) {
                v0 = gelu_tanh(v0); v1 = gelu_tanh(v1);
                v2 = gelu_tanh(v2); v3 = gelu_tanh(v3);
                size_t o0 = (size_t)row * N + col;
                size_t o1 = (size_t)(row + 8) * N + col;
                split2(v0, v1, Ch + o0, Cl + o0);
                split2(v2, v3, Ch + o1, Cl + o1);
            } else {
                *(float2*)&Cz[(size_t)row * N + col] = make_float2(v0, v1);
                *(float2*)&Cz[(size_t)(row + 8) * N + col] = make_float2(v2, v3);
            }
        }
    }
}

// ---------------- fused flash attention --------------------------------------
#define FRS 144
#define FT (128 * FRS)
#define FLASH_SMEM (4 * FT + 512)

__global__ void __launch_bounds__(256, 1) flash_attn(
    const float* __restrict__ qkv, const int* __restrict__ mask,
    __nv_bfloat16* __restrict__ Oh, __nv_bfloat16* __restrict__ Ol) {
    extern __shared__ __align__(128) char smem[];
    const uint32_t sb = smem_u32(smem);
    float* am_sm = (float*)(smem + 4 * FT);

    const int tid = threadIdx.x;
    const int wid = tid >> 5;
    const int lane = tid & 31;
    const int sub = lane >> 3, r8 = lane & 7;
    const int g = lane >> 2, tg = lane & 3;
    const int bz = blockIdx.y;
    const int b = bz / HH, h = bz % HH;
    const int m0 = (gridDim.x - 1 - blockIdx.x) * 128;

    const float* Q = qkv + (size_t)b * SS * (3 * DD) + h * DH;
    const float* Kp = Q + DD;
    const float* Vp = Q + 2 * DD;

#pragma unroll
    for (int i = 0; i < 8; i++) {
        int idx = i * 256 + tid;
        int r = idx >> 4, c4 = (idx & 15) * 4;
        float4 qv = *(const float4*)(Q + (size_t)(m0 + r) * (3 * DD) + c4);
        uint32_t off = r * FRS + c4 * 2;
        split2(qv.x, qv.y, (__nv_bfloat16*)(smem + off), (__nv_bfloat16*)(smem + FT + off));
        split2(qv.z, qv.w, (__nv_bfloat16*)(smem + off + 4), (__nv_bfloat16*)(smem + FT + off + 4));
    }
    __syncthreads();
    uint32_t qh[4][4], ql[4][4];
#pragma unroll
    for (int kf = 0; kf < 4; kf++) {
        uint32_t off = (uint32_t)((wid * 16 + r8 + (sub & 1) * 8) * FRS + kf * 32 + (sub >> 1) * 16);
        ldm4(qh[kf], sb + off);
        ldm4(ql[kf], sb + FT + off);
    }

    float mprev0 = -1e30f, mprev1 = -1e30f;
    float l0 = 0.0f, l1 = 0.0f;
    float acco[8][4];
#pragma unroll
    for (int j = 0; j < 8; j++)
#pragma unroll
        for (int k = 0; k < 4; k++) acco[j][k] = 0.0f;

    const int nch = (m0 >> 7) + 1;
    const int rowg = m0 + wid * 16 + g;

    for (int kc = 0; kc < nch; kc++) {
        const int k0 = kc * 128;
        __syncthreads();
#pragma unroll
        for (int i = 0; i < 8; i++) {
            int idx = i * 256 + tid;
            int r = idx >> 4, c4 = (idx & 15) * 4;
            float4 kv = *(const float4*)(Kp + (size_t)(k0 + r) * (3 * DD) + c4);
            float4 vv = *(const float4*)(Vp + (size_t)(k0 + r) * (3 * DD) + c4);
            uint32_t off = r * FRS + c4 * 2;
            split2(kv.x, kv.y, (__nv_bfloat16*)(smem + off), (__nv_bfloat16*)(smem + FT + off));
            split2(kv.z, kv.w, (__nv_bfloat16*)(smem + off + 4), (__nv_bfloat16*)(smem + FT + off + 4));
            split2(vv.x, vv.y, (__nv_bfloat16*)(smem + 2 * FT + off), (__nv_bfloat16*)(smem + 3 * FT + off));
            split2(vv.z, vv.w, (__nv_bfloat16*)(smem + 2 * FT + off + 4), (__nv_bfloat16*)(smem + 3 * FT + off + 4));
        }
        if (tid < 128) am_sm[tid] = (1.0f - (float)mask[b * SS + k0 + tid]) * -10000.0f;
        __syncthreads();

        float sacc[16][4];
#pragma unroll
        for (int j = 0; j < 16; j++)
#pragma unroll
            for (int k = 0; k < 4; k++) sacc[j][k] = 0.0f;

#pragma unroll
        for (int nq = 0; nq < 4; nq++) {
#pragma unroll
            for (int kfp = 0; kfp < 2; kfp++) {
                uint32_t kbh[2][4][2], kbl[2][4][2];
#pragma unroll
                for (int kf2 = 0; kf2 < 2; kf2++) {
                    int kf = kfp * 2 + kf2;
#pragma unroll
                    for (int j = 0; j < 2; j++) {
                        uint32_t off = (uint32_t)((nq * 32 + j * 16 + (sub >> 1) * 8 + r8) * FRS
                                                  + kf * 32 + (sub & 1) * 16);
                        uint32_t r[4];
                        ldm4(r, sb + off);
                        kbh[kf2][j * 2][0] = r[0]; kbh[kf2][j * 2][1] = r[1];
                        kbh[kf2][j * 2 + 1][0] = r[2]; kbh[kf2][j * 2 + 1][1] = r[3];
                        ldm4(r, sb + FT + off);
                        kbl[kf2][j * 2][0] = r[0]; kbl[kf2][j * 2][1] = r[1];
                        kbl[kf2][j * 2 + 1][0] = r[2]; kbl[kf2][j * 2 + 1][1] = r[3];
                    }
                }
#pragma unroll
                for (int kf2 = 0; kf2 < 2; kf2++)
#pragma unroll
                    for (int t = 0; t < 4; t++)
                        mma_bf16(sacc[nq * 4 + t], qh[kfp * 2 + kf2], kbh[kf2][t]);
#pragma unroll
                for (int kf2 = 0; kf2 < 2; kf2++)
#pragma unroll
                    for (int t = 0; t < 4; t++)
                        mma_bf16(sacc[nq * 4 + t], ql[kfp * 2 + kf2], kbh[kf2][t]);
#pragma unroll
                for (int kf2 = 0; kf2 < 2; kf2++)
#pragma unroll
                    for (int t = 0; t < 4; t++)
                        mma_bf16(sacc[nq * 4 + t], qh[kfp * 2 + kf2], kbl[kf2][t]);
            }
        }

        const bool diag = (kc == (m0 >> 7));
        float mx0 = -1e30f, mx1 = -1e30f;
#pragma unroll
        for (int nf = 0; nf < 16; nf++) {
            int cl = nf * 8 + tg * 2;
            float am0 = am_sm[cl], am1 = am_sm[cl + 1];
            float v0 = sacc[nf][0] * 0.125f + am0;
            float v1 = sacc[nf][1] * 0.125f + am1;
            float v2 = sacc[nf][2] * 0.125f + am0;
            float v3 = sacc[nf][3] * 0.125f + am1;
            if (diag) {
                int col = k0 + cl;
                if (col > rowg)         v0 = -10000.0f + am0;
                if (col + 1 > rowg)     v1 = -10000.0f + am1;
                if (col > rowg + 8)     v2 = -10000.0f + am0;
                if (col + 1 > rowg + 8) v3 = -10000.0f + am1;
            }
            sacc[nf][0] = v0; sacc[nf][1] = v1; sacc[nf][2] = v2; sacc[nf][3] = v3;
            mx0 = fmaxf(mx0, fmaxf(v0, v1));
            mx1 = fmaxf(mx1, fmaxf(v2, v3));
        }
        mx0 = fmaxf(mx0, __shfl_xor_sync(0xffffffffu, mx0, 1));
        mx0 = fmaxf(mx0, __shfl_xor_sync(0xffffffffu, mx0, 2));
        mx1 = fmaxf(mx1, __shfl_xor_sync(0xffffffffu, mx1, 1));
        mx1 = fmaxf(mx1, __shfl_xor_sync(0xffffffffu, mx1, 2));
        float mnew0 = fmaxf(mprev0, mx0), mnew1 = fmaxf(mprev1, mx1);
        float corr0 = __expf(mprev0 - mnew0), corr1 = __expf(mprev1 - mnew1);
        mprev0 = mnew0; mprev1 = mnew1;
        l0 *= corr0; l1 *= corr1;
#pragma unroll
        for (int nf2 = 0; nf2 < 8; nf2++) {
            acco[nf2][0] *= corr0; acco[nf2][1] *= corr0;
            acco[nf2][2] *= corr1; acco[nf2][3] *= corr1;
        }

        float ps0 = 0.0f, ps1 = 0.0f;
#pragma unroll
        for (int kt = 0; kt < 8; kt++) {
            float p00 = __expf(sacc[2 * kt][0] - mnew0);
            float p01 = __expf(sacc[2 * kt][1] - mnew0);
            float p02 = __expf(sacc[2 * kt][2] - mnew1);
            float p03 = __expf(sacc[2 * kt][3] - mnew1);
            float p10 = __expf(sacc[2 * kt + 1][0] - mnew0);
            float p11 = __expf(sacc[2 * kt + 1][1] - mnew0);
            float p12 = __expf(sacc[2 * kt + 1][2] - mnew1);
            float p13 = __expf(sacc[2 * kt + 1][3] - mnew1);
            ps0 += p00 + p01 + p10 + p11;
            ps1 += p02 + p03 + p12 + p13;
            uint32_t aph[4], apl[4];
            pack2(p00, p01, &aph[0], &apl[0]);
            pack2(p02, p03, &aph[1], &apl[1]);
            pack2(p10, p11, &aph[2], &apl[2]);
            pack2(p12, p13, &aph[3], &apl[3]);

            uint32_t vh[8][2], vl[8][2];
#pragma unroll
            for (int nt2 = 0; nt2 < 4; nt2++) {
                uint32_t off = (uint32_t)((kt * 16 + (sub & 1) * 8 + r8) * FRS
                                          + (nt2 * 16 + (sub >> 1) * 8) * 2);
                uint32_t r[4];
                ldm4t(r, sb + 2 * FT + off);
                vh[nt2 * 2][0] = r[0]; vh[nt2 * 2][1] = r[1];
                vh[nt2 * 2 + 1][0] = r[2]; vh[nt2 * 2 + 1][1] = r[3];
                ldm4t(r, sb + 3 * FT + off);
                vl[nt2 * 2][0] = r[0]; vl[nt2 * 2][1] = r[1];
                vl[nt2 * 2 + 1][0] = r[2]; vl[nt2 * 2 + 1][1] = r[3];
            }
#pragma unroll
            for (int nf2 = 0; nf2 < 8; nf2++) mma_bf16(acco[nf2], aph, vh[nf2]);
#pragma unroll
            for (int nf2 = 0; nf2 < 8; nf2++) mma_bf16(acco[nf2], apl, vh[nf2]);
#pragma unroll
            for (int nf2 = 0; nf2 < 8; nf2++) mma_bf16(acco[nf2], aph, vl[nf2]);
        }
        ps0 += __shfl_xor_sync(0xffffffffu, ps0, 1);
        ps0 += __shfl_xor_sync(0xffffffffu, ps0, 2);
        ps1 += __shfl_xor_sync(0xffffffffu, ps1, 1);
        ps1 += __shfl_xor_sync(0xffffffffu, ps1, 2);
        l0 += ps0; l1 += ps1;
    }

    float inv0 = 1.0f / l0, inv1 = 1.0f / l1;
#pragma unroll
    for (int nf2 = 0; nf2 < 8; nf2++) {
        int col = h * DH + nf2 * 8 + tg * 2;
        int row0 = m0 + wid * 16 + g;
        size_t o0 = ((size_t)(b * SS) + row0) * DD + col;
        size_t o1 = o0 + 8 * DD;
        split2(acco[nf2][0] * inv0, acco[nf2][1] * inv0, Oh + o0, Ol + o0);
        split2(acco[nf2][2] * inv1, acco[nf2][3] * inv1, Oh + o1, Ol + o1);
    }
}

// ---------------- residual add (3 partials) + LayerNorm, float4 -------------
// 192 threads, 1 float4 per stream per thread (DD = 768 = 192*4).
__global__ __launch_bounds__(192) void add_ln(
    const float* __restrict__ x, const float* __restrict__ y0,
    const float* __restrict__ y1, const float* __restrict__ y2,
    const float* __restrict__ g, const float* __restrict__ b,
    float* __restrict__ out, __nv_bfloat16* __restrict__ hi,
    __nv_bfloat16* __restrict__ lo, int do_split) {
    __shared__ float sh[6];
    int row = blockIdx.x;
    int t = threadIdx.x;
    size_t base4 = (size_t)row * (DD / 4) + t;
    float4 xv = ((const float4*)x)[base4];
    float4 a0 = ((const float4*)y0)[base4];
    float4 a1 = ((const float4*)y1)[base4];
    float4 a2 = ((const float4*)y2)[base4];
    float s0 = xv.x + (a0.x + a1.x + a2.x);
    float s1 = xv.y + (a0.y + a1.y + a2.y);
    float s2 = xv.z + (a0.z + a1.z + a2.z);
    float s3 = xv.w + (a0.w + a1.w + a2.w);
    float mean = block_sum<6>(s0 + s1 + s2 + s3, sh) * (1.0f / DD);
    float d0 = s0 - mean, d1 = s1 - mean, d2 = s2 - mean, d3 = s3 - mean;
    float var = block_sum<6>(d0 * d0 + d1 * d1 + d2 * d2 + d3 * d3, sh) * (1.0f / DD);
    float inv = rsqrtf(var + 1e-5f);
    int c = t * 4;
    float4 gv = ((const float4*)g)[t + (size_t)0 * 0 + ((size_t)(g - g))] ;
    // (load gamma/beta via direct indexing; g,b are per-layer slices)
    gv = ((const float4*)g)[t];
    float4 bv = ((const float4*)b)[t];
    float v0 = d0 * inv * gv.x + bv.x;
    float v1 = d1 * inv * gv.y + bv.y;
    float v2 = d2 * inv * gv.z + bv.z;
    float v3 = d3 * inv * gv.w + bv.w;
    ((float4*)out)[base4] = make_float4(v0, v1, v2, v3);
    if (do_split) {
        uint32_t h0, l0_, h1, l1_;
        pack2(v0, v1, &h0, &l0_);
        pack2(v2, v3, &h1, &l1_);
        size_t o = (size_t)row * DD + c;
        *(uint2*)&hi[o] = make_uint2(h0, h1);
        *(uint2*)&lo[o] = make_uint2(l0_, l1_);
    }
    (void)c;
}

// ---------------------------------------------------------------------------
extern "C" void kernel_launch(void* const* d_in, const int* in_sizes, int n_in,
                              void* d_out, int out_size) {
    const int* ids = (const int*)d_in[0];
    const int* amask = (const int*)d_in[1];
    const float* tok = (const float*)d_in[2];
    const float* pos = (const float*)d_in[3];
    const float* Wqkv = (const float*)d_in[4];
    const float* bqkv = (const float*)d_in[5];
    const float* Wo = (const float*)d_in[6];
    const float* bo = (const float*)d_in[7];
    const float* g1 = (const float*)d_in[8];
    const float* b1 = (const float*)d_in[9];
    const float* Wfc = (const float*)d_in[10];
    const float* bfc = (const float*)d_in[11];
    const float* Wp2 = (const float*)d_in[12];
    const float* bp2 = (const float*)d_in[13];
    const float* g2 = (const float*)d_in[14];
    const float* b2 = (const float*)d_in[15];
    float* out = (float*)d_out;

    float *h, *n, *qkv;
    __nv_bfloat16 *Ah, *Al, *Fh, *Fl;
    __nv_bfloat16 *Wqkv_h, *Wqkv_l, *Wo_h, *Wo_l, *Wfc_h, *Wfc_l, *Wp2_h, *Wp2_l;
    cudaGetSymbolAddress((void**)&h, g_h);
    cudaGetSymbolAddress((void**)&n, g_n);
    cudaGetSymbolAddress((void**)&qkv, g_qkv);
    cudaGetSymbolAddress((void**)&Ah, g_Ah);
    cudaGetSymbolAddress((void**)&Al, g_Al);
    cudaGetSymbolAddress((void**)&Fh, g_Fh);
    cudaGetSymbolAddress((void**)&Fl, g_Fl);
    cudaGetSymbolAddress((void**)&Wqkv_h, g_Wqkv_h);
    cudaGetSymbolAddress((void**)&Wqkv_l, g_Wqkv_l);
    cudaGetSymbolAddress((void**)&Wo_h, g_Wo_h);
    cudaGetSymbolAddress((void**)&Wo_l, g_Wo_l);
    cudaGetSymbolAddress((void**)&Wfc_h, g_Wfc_h);
    cudaGetSymbolAddress((void**)&Wfc_l, g_Wfc_l);
    cudaGetSymbolAddress((void**)&Wp2_h, g_Wp2_h);
    cudaGetSymbolAddress((void**)&Wp2_l, g_Wp2_l);

    float* q1 = qkv + (size_t)MM * DD;
    float* q2 = qkv + (size_t)2 * MM * DD;

    cudaFuncSetAttribute(gemm_mma, cudaFuncAttributeMaxDynamicSharedMemorySize, GEMM_SMEM);
    cudaFuncSetAttribute(flash_attn, cudaFuncAttributeMaxDynamicSharedMemorySize, FLASH_SMEM);

    // ---- hoisted: all 12 layers' weight transpose+split ----
    conv_wT<<<dim3((3 * DD) / 32, DD / 32, LL), 256>>>(Wqkv, Wqkv_h, Wqkv_l, DD, 3 * DD);
    conv_wT<<<dim3(DD / 32, DD / 32, LL), 256>>>(Wo, Wo_h, Wo_l, DD, DD);
    conv_wT<<<dim3(FF / 32, DD / 32, LL), 256>>>(Wfc, Wfc_h, Wfc_l, DD, FF);
    conv_wT<<<dim3(DD / 32, FF / 32, LL), 256>>>(Wp2, Wp2_h, Wp2_l, FF, DD);

    embed_kernel<<<(MM * DD / 2 + 255) / 256, 256>>>(ids, tok, pos, h, Ah, Al);

    for (int l = 0; l < LL; l++) {
        const float* bqkv_l = bqkv + (size_t)l * 3 * DD;
        const float* bo_l = bo + (size_t)l * DD;
        const float* bfc_l = bfc + (size_t)l * FF;
        const float* bp2_l = bp2 + (size_t)l * DD;
        const __nv_bfloat16* Wqh = Wqkv_h + (size_t)l * 3 * DD * DD;
        const __nv_bfloat16* Wql = Wqkv_l + (size_t)l * 3 * DD * DD;
        const __nv_bfloat16* Woh = Wo_h + (size_t)l * DD * DD;
        const __nv_bfloat16* Wol = Wo_l + (size_t)l * DD * DD;
        const __nv_bfloat16* Wfh = Wfc_h + (size_t)l * FF * DD;
        const __nv_bfloat16* Wfl = Wfc_l + (size_t)l * FF * DD;
        const __nv_bfloat16* Wph = Wp2_h + (size_t)l * DD * FF;
        const __nv_bfloat16* Wpl = Wp2_l + (size_t)l * DD * FF;

        // ---- qkv = h @ Wqkv + bqkv (288 CTAs) ----
        gemm_mma<<<dim3((3 * DD) / 128, MM / 256, 1), 256, GEMM_SMEM>>>(
            Ah, Al, Wqh, Wql, bqkv_l, qkv, nullptr, nullptr, 3 * DD, DD, 0);

        // ---- fused attention -> a (bf16 hi/lo directly) ----
        flash_attn<<<dim3(SS / 128, BH), 256, FLASH_SMEM>>>(qkv, amask, Ah, Al);

        // ---- o-proj: split-K=3 (288 CTAs) ----
        gemm_mma<<<dim3(DD / 128, MM / 256, 3), 256, GEMM_SMEM>>>(
            Ah, Al, Woh, Wol, bo_l, qkv, nullptr, nullptr, DD, DD, 0);
        add_ln<<<MM, 192>>>(h, qkv, q1, q2, g1 + (size_t)l * DD, b1 + (size_t)l * DD,
                            n, Ah, Al, 1);

        // ---- MLP ----
        gemm_mma<<<dim3(FF / 128, MM / 256, 1), 256, GEMM_SMEM>>>(
            Ah, Al, Wfh, Wfl, bfc_l, nullptr, Fh, Fl, FF, DD, 1);

        gemm_mma<<<dim3(DD / 128, MM / 256, 3), 256, GEMM_SMEM>>>(
            Fh, Fl, Wph, Wpl, bp2_l, qkv, nullptr, nullptr, DD, FF, 0);

        float* dst = (l == LL - 1) ? out : h;
        add_ln<<<MM, 192>>>(n, qkv, q1, q2, g2 + (size_t)l * DD, b2 + (size_t)l * DD,
                            dst, Ah, Al, (l == LL - 1) ? 0 : 1);
    }
}